// round 2
// baseline (speedup 1.0000x reference)
#include <cuda_runtime.h>
#include <math.h>

// ---------------------------------------------------------------------------
// SoftMoE forward, fp32 baseline.
// B=4, M=1024 tokens, D=768, E=16 experts, P=64 slots, F=3072 hidden.
// Pipeline:
//   1) logits[b,m,ep] = x[b,m,:] . phi[:,ep]                (GEMM 4096x1024x768)
//   2) dispatch = softmax over tokens m   (column softmax)
//   3) combine  = softmax over ep (row softmax) + probabilities + argmax
//   4) mix[b,ep,d]  = sum_m dispatch[b,m,ep] * x[b,m,d]      (batched, A^T)
//   5) hidden = gelu(mix @ W1 + b1)   per (b,e) group        (64x [64,768]x[768,3072])
//   6) eout   = hidden @ W2 + b2      per (b,e) group        (64x [64,3072]x[3072,768])
//   7) out[b,m,d] = sum_ep combine[b,m,ep] * eout[b,ep,d]    (batched)
// ---------------------------------------------------------------------------

namespace cfg {
constexpr int cB = 4, cM = 1024, cD = 768, cE = 16, cP = 64, cF = 3072;
constexpr int cEP = cE * cP;  // 1024
constexpr long long SZ_OUT  = (long long)cB * cM * cD;       // 3,145,728
constexpr long long SZ_PROB = (long long)cB * cM * cE;       //    65,536
constexpr long long SZ_TOP  = (long long)cB * cM;            //     4,096
constexpr long long SZ_HID  = (long long)cB * cE * cP * cF;  // 12,582,912
constexpr long long SZ_FULL = SZ_OUT + SZ_PROB + SZ_TOP + SZ_HID;  // 15,798,272
}
using namespace cfg;

// Scratch (allocation-free: __device__ globals).
__device__ float g_logits  [(size_t)cB * cM * cEP];      // 16 MB
__device__ float g_dispatch[(size_t)cB * cM * cEP];      // 16 MB
__device__ float g_combine [(size_t)cB * cM * cEP];      // 16 MB
__device__ float g_mix     [(size_t)cB * cE * cP * cD];  // 12 MB
__device__ float g_eout    [(size_t)cB * cE * cP * cD];  // 12 MB
__device__ float g_hid_fb  [(size_t)cB * cE * cP * cF];  // 50 MB fallback if out only holds `outputs`

// ---------------------------------------------------------------------------
// Tiled SGEMM: C[M,N] = op(A)[M,K] * B[K,N] (+bias[N]) (+gelu)
// op(A)=A  (row-major MxK)  when !TRANSA
// op(A)=A^T where A stored row-major KxM  when TRANSA
// Batched over blockIdx.z: A += z*sA, B += (z % bmod)*sB, C += z*sC,
//                          bias += (z % bmod)*sBias.
// Requires: M,N multiples of 64; K multiple of 16. (All shapes here satisfy.)
// ---------------------------------------------------------------------------

#define TBM 64
#define TBN 64
#define TBK 16

__device__ __forceinline__ float gelu_tanh(float x) {
    float x3 = x * x * x;
    return 0.5f * x * (1.0f + tanhf(0.7978845608028654f * (x + 0.044715f * x3)));
}

template <bool TRANSA, int ACT>
__global__ __launch_bounds__(256) void gemm_kernel(
    const float* __restrict__ A, const float* __restrict__ B,
    float* __restrict__ C, const float* __restrict__ bias,
    int Md, int Nd, int Kd,
    long long sA, long long sB, long long sC,
    int bmod, long long sBias)
{
    const int z = blockIdx.z;
    A += (long long)z * sA;
    B += (long long)(z % bmod) * sB;
    C += (long long)z * sC;
    if (bias) bias += (long long)(z % bmod) * sBias;

    __shared__ float As[TBK][TBM + 4];  // +4 keeps float4 alignment (272B rows)
    __shared__ float Bs[TBK][TBN];

    const int tx = threadIdx.x, ty = threadIdx.y;
    const int tid = ty * 16 + tx;
    const int row0 = blockIdx.y * TBM;
    const int col0 = blockIdx.x * TBN;

    float acc[4][4] = {};

    for (int k0 = 0; k0 < Kd; k0 += TBK) {
        if (!TRANSA) {
            // A row-major [Md, Kd]: contiguous along k for coalescing
            #pragma unroll
            for (int i = 0; i < 4; i++) {
                int l = tid + i * 256;
                int kk = l % TBK, mm = l / TBK;
                As[kk][mm] = A[(long long)(row0 + mm) * Kd + (k0 + kk)];
            }
        } else {
            // A stored row-major [Kd, Md]: contiguous along m
            #pragma unroll
            for (int i = 0; i < 4; i++) {
                int l = tid + i * 256;
                int ii = l % TBM, kk = l / TBM;
                As[kk][ii] = A[(long long)(k0 + kk) * Md + (row0 + ii)];
            }
        }
        #pragma unroll
        for (int i = 0; i < 4; i++) {
            int l = tid + i * 256;
            int nn = l % TBN, kk = l / TBN;
            Bs[kk][nn] = B[(long long)(k0 + kk) * Nd + (col0 + nn)];
        }
        __syncthreads();

        #pragma unroll
        for (int kk = 0; kk < TBK; kk++) {
            float4 a4 = *reinterpret_cast<const float4*>(&As[kk][ty * 4]);
            float4 b4 = *reinterpret_cast<const float4*>(&Bs[kk][tx * 4]);
            float a[4] = {a4.x, a4.y, a4.z, a4.w};
            float b[4] = {b4.x, b4.y, b4.z, b4.w};
            #pragma unroll
            for (int i = 0; i < 4; i++)
                #pragma unroll
                for (int j = 0; j < 4; j++)
                    acc[i][j] = fmaf(a[i], b[j], acc[i][j]);
        }
        __syncthreads();
    }

    #pragma unroll
    for (int i = 0; i < 4; i++) {
        int r = row0 + ty * 4 + i;
        #pragma unroll
        for (int j = 0; j < 4; j++) {
            int c = col0 + tx * 4 + j;
            float v = acc[i][j];
            if (bias) v += bias[c];
            if (ACT == 1) v = gelu_tanh(v);
            C[(long long)r * Nd + c] = v;
        }
    }
}

// ---------------------------------------------------------------------------
// dispatch = softmax over tokens m (axis 1). One block handles 32 ep-columns
// of one batch; blockDim (32,8): tx = ep within tile, ty = m-phase.
// ---------------------------------------------------------------------------
__global__ __launch_bounds__(256) void dispatch_softmax_kernel(
    const float* __restrict__ logits, float* __restrict__ dispatch)
{
    const int b = blockIdx.y;
    const int ep = blockIdx.x * 32 + threadIdx.x;
    const int tx = threadIdx.x, ty = threadIdx.y;
    const float* base = logits + (long long)b * cM * cEP + ep;
    float* obase = dispatch + (long long)b * cM * cEP + ep;

    // Online max/sum over this thread's m-slice
    float mx = -INFINITY, s = 0.0f;
    for (int m = ty; m < cM; m += 8) {
        float v = base[(long long)m * cEP];
        float nm = fmaxf(mx, v);
        s = s * expf(mx - nm) + expf(v - nm);
        mx = nm;
    }
    __shared__ float smx[8][32], ssum[8][32];
    smx[ty][tx] = mx;
    ssum[ty][tx] = s;
    __syncthreads();
    if (ty == 0) {
        float M_ = smx[0][tx], S = ssum[0][tx];
        #pragma unroll
        for (int i = 1; i < 8; i++) {
            float m2 = smx[i][tx];
            float nm = fmaxf(M_, m2);
            S = S * expf(M_ - nm) + ssum[i][tx] * expf(m2 - nm);
            M_ = nm;
        }
        smx[0][tx] = M_;
        ssum[0][tx] = 1.0f / S;
    }
    __syncthreads();
    const float gmx = smx[0][tx];
    const float inv = ssum[0][tx];
    for (int m = ty; m < cM; m += 8)
        obase[(long long)m * cEP] = expf(base[(long long)m * cEP] - gmx) * inv;
}

// ---------------------------------------------------------------------------
// combine = softmax over ep (contiguous 1024 per (b,m)); also emits
// probabilities[b,m,e] = mean_p combine and top_experts = argmax_e.
// One block per (b,m), 256 threads, 4 elements each.
// ---------------------------------------------------------------------------
__global__ __launch_bounds__(256) void combine_softmax_kernel(
    const float* __restrict__ logits, float* __restrict__ combine,
    float* __restrict__ prob, float* __restrict__ top)
{
    const long long bm = blockIdx.y * gridDim.x + blockIdx.x;  // b*cM + m
    const float* row = logits + bm * cEP;
    float* crow = combine + bm * cEP;

    __shared__ float sv[cEP];
    __shared__ float sred[8];
    __shared__ float sbc;
    __shared__ float sprob[cE];

    const int tid = threadIdx.x;
    const int lane = tid & 31, warp = tid >> 5;

    float v[4];
    float mx = -INFINITY;
    #pragma unroll
    for (int i = 0; i < 4; i++) {
        v[i] = row[tid + i * 256];
        mx = fmaxf(mx, v[i]);
    }
    #pragma unroll
    for (int off = 16; off > 0; off >>= 1)
        mx = fmaxf(mx, __shfl_xor_sync(0xffffffffu, mx, off));
    if (lane == 0) sred[warp] = mx;
    __syncthreads();
    if (tid == 0) {
        float m = sred[0];
        #pragma unroll
        for (int i = 1; i < 8; i++) m = fmaxf(m, sred[i]);
        sbc = m;
    }
    __syncthreads();
    const float gmx = sbc;

    float s = 0.0f;
    #pragma unroll
    for (int i = 0; i < 4; i++) {
        float e = expf(v[i] - gmx);
        sv[tid + i * 256] = e;
        s += e;
    }
    #pragma unroll
    for (int off = 16; off > 0; off >>= 1)
        s += __shfl_xor_sync(0xffffffffu, s, off);
    if (lane == 0) sred[warp] = s;
    __syncthreads();
    if (tid == 0) {
        float t = 0.0f;
        #pragma unroll
        for (int i = 0; i < 8; i++) t += sred[i];
        sbc = 1.0f / t;
    }
    __syncthreads();
    const float inv = sbc;

    #pragma unroll
    for (int i = 0; i < 4; i++)
        crow[tid + i * 256] = sv[tid + i * 256] * inv;

    // probabilities: warp w handles experts 2w, 2w+1 (64 slots each)
    #pragma unroll
    for (int e = warp * 2; e < warp * 2 + 2; e++) {
        float s2 = sv[e * 64 + lane] + sv[e * 64 + 32 + lane];
        #pragma unroll
        for (int off = 16; off > 0; off >>= 1)
            s2 += __shfl_xor_sync(0xffffffffu, s2, off);
        if (lane == 0) sprob[e] = s2 * inv * (1.0f / 64.0f);
    }
    __syncthreads();
    if (prob && tid < cE) prob[bm * cE + tid] = sprob[tid];
    if (top && tid == 0) {
        float best = -INFINITY;
        int bi = 0;
        #pragma unroll
        for (int e = 0; e < cE; e++) {
            if (sprob[e] > best) { best = sprob[e]; bi = e; }
        }
        top[bm] = (float)bi;
    }
}

// ---------------------------------------------------------------------------
// Host-side launch
// ---------------------------------------------------------------------------

static void launch_gemm(bool transA, int act,
                        const float* A, const float* B, float* C, const float* bias,
                        int Md, int Nd, int Kd,
                        long long sA, long long sB, long long sC,
                        int batches, int bmod, long long sBias)
{
    dim3 block(16, 16);
    dim3 grid(Nd / TBN, Md / TBM, batches);
    if (!transA) {
        if (act == 0)
            gemm_kernel<false, 0><<<grid, block>>>(A, B, C, bias, Md, Nd, Kd, sA, sB, sC, bmod, sBias);
        else
            gemm_kernel<false, 1><<<grid, block>>>(A, B, C, bias, Md, Nd, Kd, sA, sB, sC, bmod, sBias);
    } else {
        gemm_kernel<true, 0><<<grid, block>>>(A, B, C, bias, Md, Nd, Kd, sA, sB, sC, bmod, sBias);
    }
}

extern "C" void kernel_launch(void* const* d_in, const int* in_sizes, int n_in,
                              void* d_out, int out_size)
{
    const float* x   = (const float*)d_in[0];  // [B, M, D]
    const float* phi = (const float*)d_in[1];  // [D, E, P] == [D, EP]
    const float* W1  = (const float*)d_in[2];  // [E, D, F]
    const float* b1  = (const float*)d_in[3];  // [E, F]
    const float* W2  = (const float*)d_in[4];  // [E, F, D]
    const float* b2  = (const float*)d_in[5];  // [E, D]
    float* out = (float*)d_out;

    float *logits, *dispatchp, *combinep, *mixp, *eoutp, *hidfb;
    cudaGetSymbolAddress((void**)&logits,    g_logits);
    cudaGetSymbolAddress((void**)&dispatchp, g_dispatch);
    cudaGetSymbolAddress((void**)&combinep,  g_combine);
    cudaGetSymbolAddress((void**)&mixp,      g_mix);
    cudaGetSymbolAddress((void**)&eoutp,     g_eout);
    cudaGetSymbolAddress((void**)&hidfb,     g_hid_fb);

    const bool full = ((long long)out_size >= SZ_FULL);
    float* hidp  = full ? (out + SZ_OUT + SZ_PROB + SZ_TOP) : hidfb;
    float* probp = full ? (out + SZ_OUT) : nullptr;
    float* topp  = full ? (out + SZ_OUT + SZ_PROB) : nullptr;

    // 1) logits = X[4096,768] @ phi[768,1024]
    launch_gemm(false, 0, x, phi, logits, nullptr,
                cB * cM, cEP, cD, 0, 0, 0, 1, 1, 0);

    // 2) dispatch = softmax over tokens
    dispatch_softmax_kernel<<<dim3(cEP / 32, cB), dim3(32, 8)>>>(logits, dispatchp);

    // 3) combine = softmax over (e,p) + probabilities + argmax
    combine_softmax_kernel<<<dim3(cM, cB), 256>>>(logits, combinep, probp, topp);

    // 4) mix[b,ep,d] = dispatch[b]^T @ X[b]   (batched over b)
    launch_gemm(true, 0, dispatchp, x, mixp, nullptr,
                cEP, cD, cM,
                (long long)cM * cEP, (long long)cM * cD, (long long)cEP * cD,
                cB, cB, 0);

    // 5) hidden = gelu(mix @ W1 + b1)  per (b,e) group
    launch_gemm(false, 1, mixp, W1, hidp, b1,
                cP, cF, cD,
                (long long)cP * cD, (long long)cD * cF, (long long)cP * cF,
                cB * cE, cE, cF);

    // 6) eout = hidden @ W2 + b2  per (b,e) group
    launch_gemm(false, 0, hidp, W2, eoutp, b2,
                cP, cD, cF,
                (long long)cP * cF, (long long)cF * cD, (long long)cP * cD,
                cB * cE, cE, cD);

    // 7) outputs = combine[b] @ eout[b]   (batched over b)
    launch_gemm(false, 0, combinep, eoutp, out, nullptr,
                cM, cD, cEP,
                (long long)cM * cEP, (long long)cEP * cD, (long long)cM * cD,
                cB, cB, 0);
}